// round 15
// baseline (speedup 1.0000x reference)
#include <cuda_runtime.h>
#include <cuda_bf16.h>
#include <cstdint>

#define NN 100000
#define NE 800000
#define HD 128
#define SLOTS 64           // padded adjacency slots per node (Poisson(8): P(deg>40) ~ 1e-16)
#define BN_EPS 1e-5f

// ---------------- scratch (module globals; no cudaMalloc) ----------------
__device__ __align__(256) float g_xs[(size_t)NN * HD];     // dinv[i] * (x @ W)[i]
__device__ __align__(256) float g_agg[(size_t)NN * HD];    // pre-BN activations
__device__ __align__(256) int   g_src[(size_t)NN * SLOTS]; // padded incoming-edge source ids
__device__ __align__(256) int   g_cnt[NN];                 // incoming edge count (no self-loop)
__device__ __align__(256) float g_sum[HD];
__device__ __align__(256) float g_sumsq[HD];
__device__ int g_is64;                                     // edge-index dtype flag

// ---- f32x2 packed math helpers -------------------------------------------
__device__ __forceinline__ unsigned long long pack2(float lo, float hi) {
    unsigned long long r;
    asm("mov.b64 %0, {%1, %2};" : "=l"(r) : "f"(lo), "f"(hi));
    return r;
}
__device__ __forceinline__ void unpack2(unsigned long long v, float& lo, float& hi) {
    asm("mov.b64 {%0, %1}, %2;" : "=f"(lo), "=f"(hi) : "l"(v));
}
__device__ __forceinline__ unsigned long long fma2(unsigned long long a,
                                                   unsigned long long b,
                                                   unsigned long long c) {
    unsigned long long d;
    asm("fma.rn.f32x2 %0, %1, %2, %3;" : "=l"(d) : "l"(a), "l"(b), "l"(c));
    return d;
}

// ---------------- dtype detect: int64 indices have zero odd 32b words ----
__global__ void k_detect(const int* __restrict__ ew, int nwords) {
    int i = threadIdx.x;
    int nz = 0;
    for (int j = 1 + 2 * i; j < nwords && j < 8192; j += 512)
        nz |= (ew[j] != 0);
    __shared__ int s_nz;
    if (threadIdx.x == 0) s_nz = 0;
    __syncthreads();
    if (nz) atomicOr(&s_nz, 1);
    __syncthreads();
    if (threadIdx.x == 0) g_is64 = (s_nz == 0) ? 1 : 0;
}

// ---------------- init: zero counters + BN accumulators ------------------
__global__ void k_zero(int n) {
    int i = blockIdx.x * blockDim.x + threadIdx.x;
    if (i < n) g_cnt[i] = 0;
    if (i < HD) { g_sum[i] = 0.f; g_sumsq[i] = 0.f; }
}

// ---------------- build padded adjacency: src lists per target -----------
__global__ void k_fill(const void* __restrict__ ei, int E, int n) {
    int i = blockIdx.x * blockDim.x + threadIdx.x;
    if (i >= E) return;
    int r, c;
    if (g_is64) {
        const long long* e64 = (const long long*)ei;
        r = (int)e64[i];
        c = (int)e64[(size_t)E + i];
    } else {
        const int* e32 = (const int*)ei;
        r = e32[i];
        c = e32[(size_t)E + i];
    }
    if ((unsigned)r >= (unsigned)n || (unsigned)c >= (unsigned)n) return;  // never trap
    int pos = atomicAdd(&g_cnt[c], 1);
    if (pos < SLOTS) g_src[(size_t)c * SLOTS + pos] = r;
}

// ---------------- GEMM: xs = dinv * (x @ W) --------------------------------
// block = 128 threads (4 warps), tile 64 rows x 128 cols.
// warp (wr,wc): rows wr*32+[0,32), cols wc*64+[0,64).
// lane (lr,lc) = (lane&3, lane>>2): thread tile 8 rows x 8 cols.
// Per k per warp: 4 dense L1 wavefronts vs 32 FFMA2 (8:1).
__global__ void __launch_bounds__(128, 2)
k_gemm(const float* __restrict__ x, const float* __restrict__ W, int n) {
    extern __shared__ float sm[];
    float* Wsh  = sm;                 // 128*128 = 16384 floats, row-major [k][j]
    float* XshT = sm + 16384;         // 128*64  =  8192 floats, [k][r]
    float* Dsh  = sm + 16384 + 8192;  // 64 floats

    const int tid = threadIdx.x;
    const int row0 = blockIdx.x * 64;

    // stage W (4096 float4)
    for (int j = tid; j < 4096; j += 128)
        ((float4*)Wsh)[j] = ((const float4*)W)[j];

    // stage x transposed; r = lane bits -> conflict-free XshT stores (bank = r%32)
    for (int j = tid; j < 2048; j += 128) {
        int r  = j & 63;
        int kq = j >> 6;          // float4 index along k
        int gr = row0 + r;
        float4 v = (gr < n) ? ((const float4*)x)[(size_t)gr * 32 + kq]
                            : make_float4(0.f, 0.f, 0.f, 0.f);
        XshT[(kq * 4 + 0) * 64 + r] = v.x;
        XshT[(kq * 4 + 1) * 64 + r] = v.y;
        XshT[(kq * 4 + 2) * 64 + r] = v.z;
        XshT[(kq * 4 + 3) * 64 + r] = v.w;
    }
    if (tid < 64) {
        int gr = row0 + tid;
        Dsh[tid] = (gr < n) ? rsqrtf((float)(g_cnt[gr] + 1)) : 0.f;
    }
    __syncthreads();

    const int lane = tid & 31;
    const int wid  = tid >> 5;
    const int wr = wid & 1, wc = wid >> 1;
    const int lr = lane & 3, lc = lane >> 2;
    const int rbase = wr * 32 + lr * 8;      // 8 rows
    const int cbase = wc * 64 + lc * 8;      // 8 cols

    unsigned long long acc[8][4];            // [row][col-pair]
#pragma unroll
    for (int r = 0; r < 8; r++)
#pragma unroll
        for (int j = 0; j < 4; j++) acc[r][j] = 0ull;

#pragma unroll 4
    for (int k = 0; k < 128; k++) {
        float4 a0 = *(const float4*)(XshT + k * 64 + rbase);
        float4 a1 = *(const float4*)(XshT + k * 64 + rbase + 4);
        float4 w0 = *(const float4*)(Wsh + k * 128 + cbase);
        float4 w1 = *(const float4*)(Wsh + k * 128 + cbase + 4);
        unsigned long long b[4];
        b[0] = pack2(w0.x, w0.y);
        b[1] = pack2(w0.z, w0.w);
        b[2] = pack2(w1.x, w1.y);
        b[3] = pack2(w1.z, w1.w);
        float ar[8] = {a0.x, a0.y, a0.z, a0.w, a1.x, a1.y, a1.z, a1.w};
#pragma unroll
        for (int r = 0; r < 8; r++) {
            unsigned long long ad = pack2(ar[r], ar[r]);
#pragma unroll
            for (int j = 0; j < 4; j++)
                acc[r][j] = fma2(ad, b[j], acc[r][j]);
        }
    }

#pragma unroll
    for (int r = 0; r < 8; r++) {
        int gr = row0 + rbase + r;
        if (gr < n) {
            float d = Dsh[rbase + r];
            float f[8];
#pragma unroll
            for (int j = 0; j < 4; j++) unpack2(acc[r][j], f[2 * j], f[2 * j + 1]);
            float* dst = g_xs + (size_t)gr * HD + cbase;
            *(float4*)(dst)     = make_float4(f[0] * d, f[1] * d, f[2] * d, f[3] * d);
            *(float4*)(dst + 4) = make_float4(f[4] * d, f[5] * d, f[6] * d, f[7] * d);
        }
    }
}

// -------- gather aggregation + fused BN statistics ------------------------
// 256 threads = 8 warps; each warp processes 4 nodes sequentially.
// agg[i] = dinv[i] * ( xs[i] + sum_{e: col(e)=i} xs[row(e)] )
__global__ void k_agg(int n) {
    __shared__ float red[8][32][8];   // [warp][lane][s.xyzw | s2.xyzw]
    int wid = threadIdx.x >> 5;
    int lane = threadIdx.x & 31;
    int node0 = (blockIdx.x * 8 + wid) * 4;

    float4 s  = make_float4(0.f, 0.f, 0.f, 0.f);
    float4 s2 = make_float4(0.f, 0.f, 0.f, 0.f);

    for (int g = 0; g < 4; g++) {
        int node = node0 + g;
        if (node >= n) break;
        int rawcnt = g_cnt[node];
        float d = rsqrtf((float)(rawcnt + 1));
        int cnt = rawcnt > SLOTS ? SLOTS : rawcnt;
        size_t base = (size_t)node * SLOTS;

        float4 acc = *((const float4*)(g_xs + (size_t)node * HD) + lane);  // self-loop

        int srcj = (lane < cnt) ? g_src[base + lane] : 0;
        int m = cnt < 32 ? cnt : 32;
        for (int j = 0; j < m; j++) {
            int sidx = __shfl_sync(0xffffffffu, srcj, j);
            float4 v = *((const float4*)(g_xs + (size_t)sidx * HD) + lane);
            acc.x += v.x; acc.y += v.y; acc.z += v.z; acc.w += v.w;
        }
        for (int j = 32; j < cnt; j++) {       // rare tail (deg > 32)
            int sidx = g_src[base + j];
            float4 v = *((const float4*)(g_xs + (size_t)sidx * HD) + lane);
            acc.x += v.x; acc.y += v.y; acc.z += v.z; acc.w += v.w;
        }

        acc.x *= d; acc.y *= d; acc.z *= d; acc.w *= d;
        *((float4*)(g_agg + (size_t)node * HD) + lane) = acc;

        s.x += acc.x; s.y += acc.y; s.z += acc.z; s.w += acc.w;
        s2.x = fmaf(acc.x, acc.x, s2.x);
        s2.y = fmaf(acc.y, acc.y, s2.y);
        s2.z = fmaf(acc.z, acc.z, s2.z);
        s2.w = fmaf(acc.w, acc.w, s2.w);
    }

    red[wid][lane][0] = s.x;  red[wid][lane][1] = s.y;
    red[wid][lane][2] = s.z;  red[wid][lane][3] = s.w;
    red[wid][lane][4] = s2.x; red[wid][lane][5] = s2.y;
    red[wid][lane][6] = s2.z; red[wid][lane][7] = s2.w;
    __syncthreads();

    // 256 threads cover (lane2, comp, stat): sum 8 warps, one atomic each
    int lane2 = threadIdx.x & 31;
    int rest  = threadIdx.x >> 5;   // 0..7
    int comp  = rest & 3;
    int stat  = rest >> 2;          // 0 = sum, 1 = sumsq
    float v = 0.f;
#pragma unroll
    for (int w = 0; w < 8; w++) v += red[w][lane2][stat * 4 + comp];
    float* dst = (stat ? g_sumsq : g_sum) + lane2 * 4 + comp;
    atomicAdd(dst, v);
}

// ---------------- epilogue: BN finalize folded in + ReLU -----------------
// bias b shifts every row of a feature uniformly -> BatchNorm removes it
// exactly, so it is never applied.
__global__ void k_out(const float* __restrict__ gamma,
                      const float* __restrict__ beta,
                      float* __restrict__ out, int n) {
    int idx = blockIdx.x * blockDim.x + threadIdx.x;  // float4 index
    int total = n * (HD / 4);
    if (idx >= total) return;
    int fq = idx & 31;
    float inv_n = 1.0f / (float)n;
    float4 sm4 = ((const float4*)g_sum)[fq];
    float4 sq4 = ((const float4*)g_sumsq)[fq];
    float4 gm4 = ((const float4*)gamma)[fq];
    float4 bt4 = ((const float4*)beta)[fq];
    float4 sc, sh;
    {
        float mx = sm4.x * inv_n, my = sm4.y * inv_n,
              mz = sm4.z * inv_n, mw = sm4.w * inv_n;
        sc.x = gm4.x * rsqrtf(fmaf(-mx, mx, sq4.x * inv_n) + BN_EPS);
        sc.y = gm4.y * rsqrtf(fmaf(-my, my, sq4.y * inv_n) + BN_EPS);
        sc.z = gm4.z * rsqrtf(fmaf(-mz, mz, sq4.z * inv_n) + BN_EPS);
        sc.w = gm4.w * rsqrtf(fmaf(-mw, mw, sq4.w * inv_n) + BN_EPS);
        sh.x = fmaf(-mx, sc.x, bt4.x);
        sh.y = fmaf(-my, sc.y, bt4.y);
        sh.z = fmaf(-mz, sc.z, bt4.z);
        sh.w = fmaf(-mw, sc.w, bt4.w);
    }
    float4 a = ((const float4*)g_agg)[idx];
    float4 o;
    o.x = fmaxf(fmaf(a.x, sc.x, sh.x), 0.f);
    o.y = fmaxf(fmaf(a.y, sc.y, sh.y), 0.f);
    o.z = fmaxf(fmaf(a.z, sc.z, sh.z), 0.f);
    o.w = fmaxf(fmaf(a.w, sc.w, sh.w), 0.f);
    ((float4*)out)[idx] = o;
}

// --------------------------------------------------------------------------
extern "C" void kernel_launch(void* const* d_in, const int* in_sizes, int n_in,
                              void* d_out, int out_size) {
    const float* x      = (const float*)d_in[0];
    const void*  ei     = d_in[1];                 // int32 or int64, detected on device
    const float* W      = (const float*)d_in[2];
    // d_in[3] = b (cancels under BatchNorm; unused)
    const float* gamma  = (const float*)d_in[4];
    const float* beta   = (const float*)d_in[5];
    float* out          = (float*)d_out;

    const int n = in_sizes[0] / HD;   // 100000
    const int E = in_sizes[1] / 2;    // 800000

    const int smem_gemm = (16384 + 8192 + 64) * (int)sizeof(float);
    cudaFuncSetAttribute(k_gemm, cudaFuncAttributeMaxDynamicSharedMemorySize,
                         smem_gemm);

    k_detect<<<1, 256>>>((const int*)ei, 2 * E);
    k_zero<<<(n + 255) / 256, 256>>>(n);
    k_fill<<<(E + 255) / 256, 256>>>(ei, E, n);
    k_gemm<<<(n + 63) / 64, 128, smem_gemm>>>(x, W, n);
    k_agg<<<(n + 31) / 32, 256>>>(n);         // 8 warps/block, 4 nodes/warp
    k_out<<<(n * (HD / 4) + 255) / 256, 256>>>(gamma, beta, out, n);
}

// round 16
// speedup vs baseline: 1.4039x; 1.4039x over previous
#include <cuda_runtime.h>
#include <cuda_bf16.h>
#include <cstdint>

#define NN 100000
#define NE 800000
#define HD 128
#define SLOTS 64           // padded adjacency slots per node (Poisson(8): P(deg>40) ~ 1e-16)
#define BN_EPS 1e-5f

// ---------------- scratch (module globals; no cudaMalloc) ----------------
__device__ __align__(256) float g_xs[(size_t)NN * HD];     // dinv[i] * (x @ W)[i]
__device__ __align__(256) float g_agg[(size_t)NN * HD];    // pre-BN activations
__device__ __align__(256) int   g_src[(size_t)NN * SLOTS]; // padded incoming-edge source ids
__device__ __align__(256) int   g_cnt[NN];                 // incoming edge count (no self-loop)
__device__ __align__(256) float g_sum[HD];
__device__ __align__(256) float g_sumsq[HD];
__device__ int g_is64;                                     // edge-index dtype flag

// ---- f32x2 packed math helpers -------------------------------------------
__device__ __forceinline__ unsigned long long pack2(float lo, float hi) {
    unsigned long long r;
    asm("mov.b64 %0, {%1, %2};" : "=l"(r) : "f"(lo), "f"(hi));
    return r;
}
__device__ __forceinline__ void unpack2(unsigned long long v, float& lo, float& hi) {
    asm("mov.b64 {%0, %1}, %2;" : "=f"(lo), "=f"(hi) : "l"(v));
}
__device__ __forceinline__ unsigned long long fma2(unsigned long long a,
                                                   unsigned long long b,
                                                   unsigned long long c) {
    unsigned long long d;
    asm("fma.rn.f32x2 %0, %1, %2, %3;" : "=l"(d) : "l"(a), "l"(b), "l"(c));
    return d;
}

// ---------------- dtype detect: int64 indices have zero odd 32b words ----
__global__ void k_detect(const int* __restrict__ ew, int nwords) {
    int i = threadIdx.x;
    int nz = 0;
    for (int j = 1 + 2 * i; j < nwords && j < 8192; j += 512)
        nz |= (ew[j] != 0);
    __shared__ int s_nz;
    if (threadIdx.x == 0) s_nz = 0;
    __syncthreads();
    if (nz) atomicOr(&s_nz, 1);
    __syncthreads();
    if (threadIdx.x == 0) g_is64 = (s_nz == 0) ? 1 : 0;
}

// ---------------- init: zero counters + BN accumulators ------------------
__global__ void k_zero(int n) {
    int i = blockIdx.x * blockDim.x + threadIdx.x;
    if (i < n) g_cnt[i] = 0;
    if (i < HD) { g_sum[i] = 0.f; g_sumsq[i] = 0.f; }
}

// ---------------- build padded adjacency: src lists per target -----------
__global__ void k_fill(const void* __restrict__ ei, int E, int n) {
    int i = blockIdx.x * blockDim.x + threadIdx.x;
    if (i >= E) return;
    int r, c;
    if (g_is64) {
        const long long* e64 = (const long long*)ei;
        r = (int)e64[i];
        c = (int)e64[(size_t)E + i];
    } else {
        const int* e32 = (const int*)ei;
        r = e32[i];
        c = e32[(size_t)E + i];
    }
    if ((unsigned)r >= (unsigned)n || (unsigned)c >= (unsigned)n) return;  // never trap
    int pos = atomicAdd(&g_cnt[c], 1);
    if (pos < SLOTS) g_src[(size_t)c * SLOTS + pos] = r;
}

// ---------------- GEMM: xs = dinv * (x @ W) --------------------------------
// block = 128 threads (4 warps), tile 64 rows x 128 cols.
// W is NOT staged in smem: identical across blocks -> __ldg float4, L1-hot.
// smem = XshT only (32KB) -> 4-6 blocks/SM instead of 2.
// warp w: rows w*16+[0,16); lane (lr,lc) = (lane&1, lane>>1): 8x8 thread tile.
__global__ void __launch_bounds__(128, 4)
k_gemm(const float* __restrict__ x, const float* __restrict__ W, int n) {
    extern __shared__ float sm[];
    float* XshT = sm;            // 128*64 floats, [k][r]
    float* Dsh  = sm + 8192;     // 64 floats

    const int tid = threadIdx.x;
    const int row0 = blockIdx.x * 64;

    // stage x transposed; r = low bits -> conflict-free XshT stores (bank = r%32)
    for (int j = tid; j < 2048; j += 128) {
        int r  = j & 63;
        int kq = j >> 6;          // float4 index along k
        int gr = row0 + r;
        float4 v = (gr < n) ? ((const float4*)x)[(size_t)gr * 32 + kq]
                            : make_float4(0.f, 0.f, 0.f, 0.f);
        XshT[(kq * 4 + 0) * 64 + r] = v.x;
        XshT[(kq * 4 + 1) * 64 + r] = v.y;
        XshT[(kq * 4 + 2) * 64 + r] = v.z;
        XshT[(kq * 4 + 3) * 64 + r] = v.w;
    }
    if (tid < 64) {
        int gr = row0 + tid;
        Dsh[tid] = (gr < n) ? rsqrtf((float)(g_cnt[gr] + 1)) : 0.f;
    }
    __syncthreads();

    const int lane = tid & 31;
    const int wid  = tid >> 5;
    const int lr = lane & 1, lc = lane >> 1;      // 2 row-groups x 16 col-groups
    const int rbase = wid * 16 + lr * 8;          // 8 rows
    const int cbase = lc * 8;                     // 8 cols

    unsigned long long acc[8][4];                 // [row][col-pair]
#pragma unroll
    for (int r = 0; r < 8; r++)
#pragma unroll
        for (int j = 0; j < 4; j++) acc[r][j] = 0ull;

#pragma unroll 4
    for (int k = 0; k < 128; k++) {
        float4 a0 = *(const float4*)(XshT + k * 64 + rbase);
        float4 a1 = *(const float4*)(XshT + k * 64 + rbase + 4);
        float4 w0 = __ldg((const float4*)(W + k * 128 + cbase));
        float4 w1 = __ldg((const float4*)(W + k * 128 + cbase + 4));
        unsigned long long b[4];
        b[0] = pack2(w0.x, w0.y);                 // aligned pairs: no extra MOVs
        b[1] = pack2(w0.z, w0.w);
        b[2] = pack2(w1.x, w1.y);
        b[3] = pack2(w1.z, w1.w);
        float ar[8] = {a0.x, a0.y, a0.z, a0.w, a1.x, a1.y, a1.z, a1.w};
#pragma unroll
        for (int r = 0; r < 8; r++) {
            unsigned long long ad = pack2(ar[r], ar[r]);
#pragma unroll
            for (int j = 0; j < 4; j++)
                acc[r][j] = fma2(ad, b[j], acc[r][j]);
        }
    }

#pragma unroll
    for (int r = 0; r < 8; r++) {
        int gr = row0 + rbase + r;
        if (gr < n) {
            float d = Dsh[rbase + r];
            float f[8];
#pragma unroll
            for (int j = 0; j < 4; j++) unpack2(acc[r][j], f[2 * j], f[2 * j + 1]);
            float* dst = g_xs + (size_t)gr * HD + cbase;
            *(float4*)(dst)     = make_float4(f[0] * d, f[1] * d, f[2] * d, f[3] * d);
            *(float4*)(dst + 4) = make_float4(f[4] * d, f[5] * d, f[6] * d, f[7] * d);
        }
    }
}

// ---------------- gather aggregation: one warp per node (proven form) ----
// agg[i] = dinv[i] * ( xs[i] + sum_{e: col(e)=i} xs[row(e)] )
__global__ void k_agg(int n) {
    int warp = (blockIdx.x * blockDim.x + threadIdx.x) >> 5;
    int lane = threadIdx.x & 31;
    if (warp >= n) return;

    int rawcnt = g_cnt[warp];
    float d = rsqrtf((float)(rawcnt + 1));
    int cnt = rawcnt > SLOTS ? SLOTS : rawcnt;
    size_t base = (size_t)warp * SLOTS;

    // self-loop message
    float4 acc = *((const float4*)(g_xs + (size_t)warp * HD) + lane);

    // prefetch up to 32 source ids, one per lane; broadcast via shfl
    int srcj = (lane < cnt) ? g_src[base + lane] : 0;
    int m = cnt < 32 ? cnt : 32;
    for (int j = 0; j < m; j++) {
        int s = __shfl_sync(0xffffffffu, srcj, j);
        float4 v = *((const float4*)(g_xs + (size_t)s * HD) + lane);
        acc.x += v.x; acc.y += v.y; acc.z += v.z; acc.w += v.w;
    }
    for (int j = 32; j < cnt; j++) {           // rare tail (deg > 32)
        int s = g_src[base + j];
        float4 v = *((const float4*)(g_xs + (size_t)s * HD) + lane);
        acc.x += v.x; acc.y += v.y; acc.z += v.z; acc.w += v.w;
    }

    acc.x *= d; acc.y *= d; acc.z *= d; acc.w *= d;
    *((float4*)(g_agg + (size_t)warp * HD) + lane) = acc;
}

// ---------------- BN batch statistics: float4 rows, block-reduced ---------
__global__ void k_stats(int n) {
    __shared__ float red[8][32][8];   // [sub][fq][s.xyzw | s2.xyzw]
    int fq  = threadIdx.x & 31;       // float4 index within feature dim
    int sub = threadIdx.x >> 5;       // 0..7 (warp id): row subgroup
    float4 s  = make_float4(0.f, 0.f, 0.f, 0.f);
    float4 s2 = make_float4(0.f, 0.f, 0.f, 0.f);
    for (int r = blockIdx.x * 8 + sub; r < n; r += gridDim.x * 8) {
        float4 v = ((const float4*)g_agg)[(size_t)r * 32 + fq];
        s.x += v.x; s.y += v.y; s.z += v.z; s.w += v.w;
        s2.x = fmaf(v.x, v.x, s2.x);
        s2.y = fmaf(v.y, v.y, s2.y);
        s2.z = fmaf(v.z, v.z, s2.z);
        s2.w = fmaf(v.w, v.w, s2.w);
    }
    red[sub][fq][0] = s.x;  red[sub][fq][1] = s.y;
    red[sub][fq][2] = s.z;  red[sub][fq][3] = s.w;
    red[sub][fq][4] = s2.x; red[sub][fq][5] = s2.y;
    red[sub][fq][6] = s2.z; red[sub][fq][7] = s2.w;
    __syncthreads();

    // 256 threads cover (fq2, comp, stat): sum the 8 subgroups, one atomic each
    int fq2  = threadIdx.x & 31;
    int rest = threadIdx.x >> 5;
    int comp = rest & 3;
    int stat = rest >> 2;             // 0 = sum, 1 = sumsq
    float v = 0.f;
#pragma unroll
    for (int w = 0; w < 8; w++) v += red[w][fq2][stat * 4 + comp];
    float* dst = (stat ? g_sumsq : g_sum) + fq2 * 4 + comp;
    atomicAdd(dst, v);
}

// ---------------- epilogue: BN finalize folded in + ReLU -----------------
// bias b shifts every row of a feature uniformly -> BatchNorm removes it
// exactly, so it is never applied.
__global__ void k_out(const float* __restrict__ gamma,
                      const float* __restrict__ beta,
                      float* __restrict__ out, int n) {
    int idx = blockIdx.x * blockDim.x + threadIdx.x;  // float4 index
    int total = n * (HD / 4);
    if (idx >= total) return;
    int fq = idx & 31;
    float inv_n = 1.0f / (float)n;
    float4 sm4 = ((const float4*)g_sum)[fq];
    float4 sq4 = ((const float4*)g_sumsq)[fq];
    float4 gm4 = ((const float4*)gamma)[fq];
    float4 bt4 = ((const float4*)beta)[fq];
    float4 sc, sh;
    {
        float mx = sm4.x * inv_n, my = sm4.y * inv_n,
              mz = sm4.z * inv_n, mw = sm4.w * inv_n;
        sc.x = gm4.x * rsqrtf(fmaf(-mx, mx, sq4.x * inv_n) + BN_EPS);
        sc.y = gm4.y * rsqrtf(fmaf(-my, my, sq4.y * inv_n) + BN_EPS);
        sc.z = gm4.z * rsqrtf(fmaf(-mz, mz, sq4.z * inv_n) + BN_EPS);
        sc.w = gm4.w * rsqrtf(fmaf(-mw, mw, sq4.w * inv_n) + BN_EPS);
        sh.x = fmaf(-mx, sc.x, bt4.x);
        sh.y = fmaf(-my, sc.y, bt4.y);
        sh.z = fmaf(-mz, sc.z, bt4.z);
        sh.w = fmaf(-mw, sc.w, bt4.w);
    }
    float4 a = ((const float4*)g_agg)[idx];
    float4 o;
    o.x = fmaxf(fmaf(a.x, sc.x, sh.x), 0.f);
    o.y = fmaxf(fmaf(a.y, sc.y, sh.y), 0.f);
    o.z = fmaxf(fmaf(a.z, sc.z, sh.z), 0.f);
    o.w = fmaxf(fmaf(a.w, sc.w, sh.w), 0.f);
    ((float4*)out)[idx] = o;
}

// --------------------------------------------------------------------------
extern "C" void kernel_launch(void* const* d_in, const int* in_sizes, int n_in,
                              void* d_out, int out_size) {
    const float* x      = (const float*)d_in[0];
    const void*  ei     = d_in[1];                 // int32 or int64, detected on device
    const float* W      = (const float*)d_in[2];
    // d_in[3] = b (cancels under BatchNorm; unused)
    const float* gamma  = (const float*)d_in[4];
    const float* beta   = (const float*)d_in[5];
    float* out          = (float*)d_out;

    const int n = in_sizes[0] / HD;   // 100000
    const int E = in_sizes[1] / 2;    // 800000

    const int smem_gemm = (8192 + 64) * (int)sizeof(float);
    cudaFuncSetAttribute(k_gemm, cudaFuncAttributeMaxDynamicSharedMemorySize,
                         smem_gemm);

    k_detect<<<1, 256>>>((const int*)ei, 2 * E);
    k_zero<<<(n + 255) / 256, 256>>>(n);
    k_fill<<<(E + 255) / 256, 256>>>(ei, E, n);
    k_gemm<<<(n + 63) / 64, 128, smem_gemm>>>(x, W, n);
    k_agg<<<(n + 7) / 8, 256>>>(n);           // one warp per node
    k_stats<<<592, 256>>>(n);
    k_out<<<(n * (HD / 4) + 255) / 256, 256>>>(gamma, beta, out, n);
}